// round 3
// baseline (speedup 1.0000x reference)
#include <cuda_runtime.h>

// BLIF: v[t] = exp(-exp(A_log[c])) * v[t-1] + x[t]
//       s[t] = (v[t] > 1)
//       out[0] = s[0]; out[t] = s[t] * (1 - s[t-1])   (pre-mask spikes)
//
// x: [T=256, B=8, C=128, H=14, W=14] f32, A_log: [128] f32, out: same shape.
// Streaming scan; float2 lanes (2x threads vs float4) + double-buffered chunks.

#define T_LEN  256
#define PIX    200704          // B*C*H*W
#define P2     (PIX / 2)       // 100352 float2 lanes; H*W=196 % 2 == 0 -> one channel per lane
#define CHUNK  8
#define NCHUNK (T_LEN / CHUNK) // 32

__device__ __forceinline__ void load_chunk(float2 (&buf)[CHUNK],
                                           const float2* __restrict__ xp, int t0)
{
    #pragma unroll
    for (int j = 0; j < CHUNK; j++)
        buf[j] = __ldcs(xp + (t0 + j) * P2);
}

__device__ __forceinline__ void compute_store_chunk(const float2 (&buf)[CHUNK],
                                                    float2* __restrict__ op, int t0,
                                                    float d,
                                                    float& vx, float& vy,
                                                    float& px, float& py)
{
    #pragma unroll
    for (int j = 0; j < CHUNK; j++) {
        vx = fmaf(d, vx, buf[j].x);
        vy = fmaf(d, vy, buf[j].y);

        float sx = (vx > 1.0f) ? 1.0f : 0.0f;
        float sy = (vy > 1.0f) ? 1.0f : 0.0f;

        float2 o;
        o.x = sx * (1.0f - px);
        o.y = sy * (1.0f - py);

        px = sx; py = sy;

        __stcs(op + (t0 + j) * P2, o);
    }
}

__global__ __launch_bounds__(256, 1)
void blif_scan_kernel(const float* __restrict__ x,
                      const float* __restrict__ A_log,
                      float* __restrict__ out)
{
    int p2 = blockIdx.x * blockDim.x + threadIdx.x;
    if (p2 >= P2) return;

    int c = (p2 / 98) & 127;   // 98 float2 lanes per (b,c) plane of 196 px

    double a = exp((double)A_log[c]);
    float d = (float)exp(-a);

    const float2* __restrict__ xp = reinterpret_cast<const float2*>(x) + p2;
    float2*       __restrict__ op = reinterpret_cast<float2*>(out) + p2;

    float vx = 0.f, vy = 0.f;
    float px = 0.f, py = 0.f;

    float2 bufA[CHUNK], bufB[CHUNK];

    load_chunk(bufA, xp, 0);

    #pragma unroll 1
    for (int i = 0; i < NCHUNK; i += 2) {
        load_chunk(bufB, xp, (i + 1) * CHUNK);
        compute_store_chunk(bufA, op, i * CHUNK, d, vx, vy, px, py);
        if (i + 2 < NCHUNK)
            load_chunk(bufA, xp, (i + 2) * CHUNK);
        compute_store_chunk(bufB, op, (i + 1) * CHUNK, d, vx, vy, px, py);
    }
}

extern "C" void kernel_launch(void* const* d_in, const int* in_sizes, int n_in,
                              void* d_out, int out_size)
{
    const float* x     = (const float*)d_in[0];
    const float* A_log = (const float*)d_in[1];
    float*       out   = (float*)d_out;

    const int threads = 256;
    const int blocks  = (P2 + threads - 1) / threads;   // 392
    blif_scan_kernel<<<blocks, threads>>>(x, A_log, out);
}

// round 4
// speedup vs baseline: 1.0776x; 1.0776x over previous
#include <cuda_runtime.h>

// BLIF: v[t] = exp(-exp(A_log[c])) * v[t-1] + x[t]
//       s[t] = (v[t] > 1)
//       out[0] = s[0]; out[t] = s[t] * (1 - s[t-1])   (pre-mask spikes)
//
// x: [T=256, B=8, C=128, H=14, W=14] f32, A_log: [128] f32, out: same shape.
// float4 lanes, double-buffered chunks, 1-warp blocks for fine-grained SM balance.

#define T_LEN  256
#define PIX    200704          // B*C*H*W
#define P4     (PIX / 4)       // 50176 float4 lanes; H*W=196 % 4 == 0 -> one channel per lane
#define CHUNK  8
#define NCHUNK (T_LEN / CHUNK) // 32

__device__ __forceinline__ void load_chunk(float4 (&buf)[CHUNK],
                                           const float4* __restrict__ xp, int t0)
{
    #pragma unroll
    for (int j = 0; j < CHUNK; j++)
        buf[j] = __ldcs(xp + (t0 + j) * P4);
}

__device__ __forceinline__ void compute_store_chunk(const float4 (&buf)[CHUNK],
                                                    float4* __restrict__ op, int t0,
                                                    float d,
                                                    float& vx, float& vy, float& vz, float& vw,
                                                    float& px, float& py, float& pz, float& pw)
{
    #pragma unroll
    for (int j = 0; j < CHUNK; j++) {
        vx = fmaf(d, vx, buf[j].x);
        vy = fmaf(d, vy, buf[j].y);
        vz = fmaf(d, vz, buf[j].z);
        vw = fmaf(d, vw, buf[j].w);

        float sx = (vx > 1.0f) ? 1.0f : 0.0f;
        float sy = (vy > 1.0f) ? 1.0f : 0.0f;
        float sz = (vz > 1.0f) ? 1.0f : 0.0f;
        float sw = (vw > 1.0f) ? 1.0f : 0.0f;

        float4 o;
        o.x = sx * (1.0f - px);
        o.y = sy * (1.0f - py);
        o.z = sz * (1.0f - pz);
        o.w = sw * (1.0f - pw);

        px = sx; py = sy; pz = sz; pw = sw;

        __stcs(op + (t0 + j) * P4, o);
    }
}

__global__ __launch_bounds__(32, 1)
void blif_scan_kernel(const float* __restrict__ x,
                      const float* __restrict__ A_log,
                      float* __restrict__ out)
{
    int p4 = blockIdx.x * 32 + threadIdx.x;
    if (p4 >= P4) return;

    int c = (p4 / 49) & 127;   // 49 float4 lanes per (b,c) plane of 196 px

    double a = exp((double)A_log[c]);
    float d = (float)exp(-a);

    const float4* __restrict__ xp = reinterpret_cast<const float4*>(x) + p4;
    float4*       __restrict__ op = reinterpret_cast<float4*>(out) + p4;

    float vx = 0.f, vy = 0.f, vz = 0.f, vw = 0.f;
    float px = 0.f, py = 0.f, pz = 0.f, pw = 0.f;

    float4 bufA[CHUNK], bufB[CHUNK];

    load_chunk(bufA, xp, 0);

    #pragma unroll 1
    for (int i = 0; i < NCHUNK; i += 2) {
        load_chunk(bufB, xp, (i + 1) * CHUNK);
        compute_store_chunk(bufA, op, i * CHUNK, d, vx, vy, vz, vw, px, py, pz, pw);
        if (i + 2 < NCHUNK)
            load_chunk(bufA, xp, (i + 2) * CHUNK);
        compute_store_chunk(bufB, op, (i + 1) * CHUNK, d, vx, vy, vz, vw, px, py, pz, pw);
    }
}

extern "C" void kernel_launch(void* const* d_in, const int* in_sizes, int n_in,
                              void* d_out, int out_size)
{
    const float* x     = (const float*)d_in[0];
    const float* A_log = (const float*)d_in[1];
    float*       out   = (float*)d_out;

    const int threads = 32;
    const int blocks  = (P4 + threads - 1) / threads;   // 1568 one-warp blocks
    blif_scan_kernel<<<blocks, threads>>>(x, A_log, out);
}

// round 5
// speedup vs baseline: 1.1147x; 1.0344x over previous
#include <cuda_runtime.h>

// BLIF: v[t] = exp(-exp(A_log[c])) * v[t-1] + x[t]
//       s[t] = (v[t] > 1)
//       out[0] = s[0]; out[t] = s[t] * (1 - s[t-1])   (pre-mask spikes)
//
// x: [T=256, B=8, C=128, H=14, W=14] f32, A_log: [128] f32, out: same shape.
// float4 lanes, CHUNK=16 double-buffered register pipeline, 1-warp blocks.

#define T_LEN  256
#define PIX    200704          // B*C*H*W
#define P4     (PIX / 4)       // 50176 float4 lanes; H*W=196 % 4 == 0 -> one channel per lane
#define CHUNK  16
#define NCHUNK (T_LEN / CHUNK) // 16

__device__ __forceinline__ void load_chunk(float4 (&buf)[CHUNK],
                                           const float4* __restrict__ xp, int t0)
{
    #pragma unroll
    for (int j = 0; j < CHUNK; j++)
        buf[j] = __ldcs(xp + (t0 + j) * P4);
}

__device__ __forceinline__ void compute_store_chunk(const float4 (&buf)[CHUNK],
                                                    float4* __restrict__ op, int t0,
                                                    float d,
                                                    float& vx, float& vy, float& vz, float& vw,
                                                    float& px, float& py, float& pz, float& pw)
{
    #pragma unroll
    for (int j = 0; j < CHUNK; j++) {
        vx = fmaf(d, vx, buf[j].x);
        vy = fmaf(d, vy, buf[j].y);
        vz = fmaf(d, vz, buf[j].z);
        vw = fmaf(d, vw, buf[j].w);

        float sx = (vx > 1.0f) ? 1.0f : 0.0f;
        float sy = (vy > 1.0f) ? 1.0f : 0.0f;
        float sz = (vz > 1.0f) ? 1.0f : 0.0f;
        float sw = (vw > 1.0f) ? 1.0f : 0.0f;

        float4 o;
        o.x = sx * (1.0f - px);
        o.y = sy * (1.0f - py);
        o.z = sz * (1.0f - pz);
        o.w = sw * (1.0f - pw);

        px = sx; py = sy; pz = sz; pw = sw;

        __stcs(op + (t0 + j) * P4, o);
    }
}

__global__ __launch_bounds__(32, 1)
void blif_scan_kernel(const float* __restrict__ x,
                      const float* __restrict__ A_log,
                      float* __restrict__ out)
{
    int p4 = blockIdx.x * 32 + threadIdx.x;
    if (p4 >= P4) return;

    int c = (p4 / 49) & 127;   // 49 float4 lanes per (b,c) plane of 196 px

    double a = exp((double)A_log[c]);
    float d = (float)exp(-a);

    const float4* __restrict__ xp = reinterpret_cast<const float4*>(x) + p4;
    float4*       __restrict__ op = reinterpret_cast<float4*>(out) + p4;

    float vx = 0.f, vy = 0.f, vz = 0.f, vw = 0.f;
    float px = 0.f, py = 0.f, pz = 0.f, pw = 0.f;

    float4 bufA[CHUNK], bufB[CHUNK];

    load_chunk(bufA, xp, 0);

    #pragma unroll 1
    for (int i = 0; i < NCHUNK; i += 2) {
        load_chunk(bufB, xp, (i + 1) * CHUNK);
        compute_store_chunk(bufA, op, i * CHUNK, d, vx, vy, vz, vw, px, py, pz, pw);
        if (i + 2 < NCHUNK)
            load_chunk(bufA, xp, (i + 2) * CHUNK);
        compute_store_chunk(bufB, op, (i + 1) * CHUNK, d, vx, vy, vz, vw, px, py, pz, pw);
    }
}

extern "C" void kernel_launch(void* const* d_in, const int* in_sizes, int n_in,
                              void* d_out, int out_size)
{
    const float* x     = (const float*)d_in[0];
    const float* A_log = (const float*)d_in[1];
    float*       out   = (float*)d_out;

    const int threads = 32;
    const int blocks  = (P4 + threads - 1) / threads;   // 1568 one-warp blocks
    blif_scan_kernel<<<blocks, threads>>>(x, A_log, out);
}